// round 2
// baseline (speedup 1.0000x reference)
#include <cuda_runtime.h>
#include <cuda_bf16.h>
#include <cstdint>

// ---------------------------------------------------------------------------
// DeltaOnlyModel: B=256, L=2048, H=V=64.
// Everything per-token in the encoder depends only on the token id (vocab=64),
// so we precompute 64-entry tables for k (normalized), v, q, and the gate
// threshold (0.4*||v||)^2. The sequential scan then runs one block per batch
// element with M held entirely in registers (row per thread), packed f32x2.
// ---------------------------------------------------------------------------

#define H 64
#define V 64
#define L 2048
#define B 256

__device__ float g_ktab[V * H];
__device__ float g_vtab[V * H];
__device__ float g_qtab[V * H];
__device__ float g_thr2[V];

typedef unsigned long long ull;

__device__ __forceinline__ ull ffma2(ull a, ull b, ull c) {
    ull d;
    asm("fma.rn.f32x2 %0, %1, %2, %3;" : "=l"(d) : "l"(a), "l"(b), "l"(c));
    return d;
}
__device__ __forceinline__ ull fadd2(ull a, ull b) {
    ull d;
    asm("add.rn.f32x2 %0, %1, %2;" : "=l"(d) : "l"(a), "l"(b));
    return d;
}
__device__ __forceinline__ ull pack2(float lo, float hi) {
    ull d;
    asm("mov.b64 %0, {%1, %2};" : "=l"(d) : "f"(lo), "f"(hi));
    return d;
}
__device__ __forceinline__ void unpack2(ull a, float& lo, float& hi) {
    asm("mov.b64 {%0, %1}, %2;" : "=f"(lo), "=f"(hi) : "l"(a));
}

// ---------------------------------------------------------------------------
// Table builder: one block per vocab entry, 64 threads.
// h = LN(e + FFN(e)); k = normalize(h@wk); v = h@wv; q = h@wq.
// ---------------------------------------------------------------------------
__global__ void build_tables(const float* __restrict__ embed,
                             const float* __restrict__ w1,
                             const float* __restrict__ b1,
                             const float* __restrict__ w2,
                             const float* __restrict__ b2,
                             const float* __restrict__ ln_g,
                             const float* __restrict__ ln_b,
                             const float* __restrict__ wk,
                             const float* __restrict__ wv,
                             const float* __restrict__ wq) {
    __shared__ float se[H];
    __shared__ float su[2 * H];
    __shared__ float sh[H];
    __shared__ float sred[H];

    const int c = blockIdx.x;
    const int j = threadIdx.x;

    se[j] = embed[c * H + j];
    __syncthreads();

    // u = relu(e @ w1 + b1)  (w1: [H, 2H])
    #pragma unroll
    for (int rep = 0; rep < 2; rep++) {
        const int m = j + rep * H;
        float a = b1[m];
        #pragma unroll 8
        for (int i = 0; i < H; i++) a = fmaf(se[i], w1[i * (2 * H) + m], a);
        su[m] = fmaxf(a, 0.0f);
    }
    __syncthreads();

    // f = u @ w2 + b2  (w2: [2H, H])
    float f = b2[j];
    #pragma unroll 8
    for (int m = 0; m < 2 * H; m++) f = fmaf(su[m], w2[m * H + j], f);

    const float s = se[j] + f;
    sh[j] = s;
    __syncthreads();

    // LayerNorm (every thread recomputes the tiny reductions)
    float mu = 0.0f;
    #pragma unroll 8
    for (int i = 0; i < H; i++) mu += sh[i];
    mu *= (1.0f / H);
    float var = 0.0f;
    #pragma unroll 8
    for (int i = 0; i < H; i++) { float d = sh[i] - mu; var = fmaf(d, d, var); }
    var *= (1.0f / H);
    const float hn = (s - mu) * rsqrtf(var + 1e-5f) * ln_g[j] + ln_b[j];
    __syncthreads();
    sh[j] = hn;
    __syncthreads();

    // k projection + L2 normalize
    float kr = 0.0f;
    #pragma unroll 8
    for (int i = 0; i < H; i++) kr = fmaf(sh[i], wk[i * H + j], kr);
    sred[j] = kr * kr;
    __syncthreads();
    float nk = 0.0f;
    #pragma unroll 8
    for (int i = 0; i < H; i++) nk += sred[i];
    nk = fmaxf(sqrtf(nk), 1e-12f);
    g_ktab[c * H + j] = kr / nk;
    __syncthreads();

    // v projection + threshold (0.4*||v||)^2 = 0.16*||v||^2
    float vr = 0.0f;
    #pragma unroll 8
    for (int i = 0; i < H; i++) vr = fmaf(sh[i], wv[i * H + j], vr);
    g_vtab[c * H + j] = vr;
    sred[j] = vr * vr;
    __syncthreads();
    float nv = 0.0f;
    #pragma unroll 8
    for (int i = 0; i < H; i++) nv += sred[i];
    if (j == 0) g_thr2[c] = 0.16f * nv;

    // q projection
    float qr = 0.0f;
    #pragma unroll 8
    for (int i = 0; i < H; i++) qr = fmaf(sh[i], wq[i * H + j], qr);
    g_qtab[c * H + j] = qr;
}

// ---------------------------------------------------------------------------
// Sequential scan: one block per batch element, 64 threads (2 warps).
// Thread i owns M row i, packed as 32 f32x2 registers.
// ---------------------------------------------------------------------------
__global__ __launch_bounds__(64) void scan_kernel(const int* __restrict__ x,
                                                  const float* __restrict__ wo,
                                                  const float* __restrict__ bo,
                                                  float* __restrict__ out) {
    __shared__ float sk[V * H];     // 16 KB, normalized k table
    __shared__ float sv[V * H];     // 16 KB, v table
    __shared__ float sthr2[V];
    __shared__ int   sx[L];         // 8 KB token ids for this batch row
    __shared__ float sred[2][2];    // double-buffered cross-warp partials
    __shared__ float sfin[H];

    const int b   = blockIdx.x;
    const int tid = threadIdx.x;
    const int lane = tid & 31;
    const int w    = tid >> 5;

    for (int i = tid; i < V * H; i += 64) {
        sk[i] = g_ktab[i];
        sv[i] = g_vtab[i];
    }
    sthr2[tid] = g_thr2[tid];
    const int* xb = x + b * L;
    for (int i = tid; i < L; i += 64) sx[i] = xb[i];
    __syncthreads();

    ull m2[H / 2];
    #pragma unroll
    for (int j = 0; j < H / 2; j++) m2[j] = 0ULL;

    for (int t = 0; t < L; t++) {
        const int tok = sx[t];
        const ulonglong2* kp = reinterpret_cast<const ulonglong2*>(sk + (tok << 6));

        // pred_i = sum_j M[i][j] * k[j]   (8 packed accumulator lanes)
        ull a0 = 0, a1 = 0, a2 = 0, a3 = 0;
        #pragma unroll
        for (int j = 0; j < 8; j++) {
            const ulonglong2 kA = kp[2 * j];
            const ulonglong2 kB = kp[2 * j + 1];
            a0 = ffma2(m2[4 * j + 0], kA.x, a0);
            a1 = ffma2(m2[4 * j + 1], kA.y, a1);
            a2 = ffma2(m2[4 * j + 2], kB.x, a2);
            a3 = ffma2(m2[4 * j + 3], kB.y, a3);
        }
        const ull accp = fadd2(fadd2(a0, a1), fadd2(a2, a3));
        float plo, phi;
        unpack2(accp, plo, phi);
        const float pred = plo + phi;

        const float delta = sv[(tok << 6) + tid] - pred;

        // ||delta||^2 across 64 threads: warp butterfly + cross-warp exchange
        float s = delta * delta;
        #pragma unroll
        for (int o = 16; o > 0; o >>= 1) s += __shfl_xor_sync(0xffffffffu, s, o);
        const int pb = t & 1;
        if (lane == 0) sred[pb][w] = s;
        __syncthreads();
        const float tot = sred[pb][0] + sred[pb][1];

        if (tot > sthr2[tok]) {
            const ull d2 = pack2(delta, delta);
            #pragma unroll
            for (int j = 0; j < 8; j++) {
                const ulonglong2 kA = kp[2 * j];
                const ulonglong2 kB = kp[2 * j + 1];
                m2[4 * j + 0] = ffma2(d2, kA.x, m2[4 * j + 0]);
                m2[4 * j + 1] = ffma2(d2, kA.y, m2[4 * j + 1]);
                m2[4 * j + 2] = ffma2(d2, kB.x, m2[4 * j + 2]);
                m2[4 * j + 3] = ffma2(d2, kB.y, m2[4 * j + 3]);
            }
        }
    }

    // Readout: q = q_tab[last token]; read = relu(M q); out = read @ wo + bo
    const int tokL = sx[L - 1];
    const float* qv = g_qtab + (tokL << 6);
    float r = 0.0f;
    #pragma unroll
    for (int j = 0; j < H / 2; j++) {
        float lo, hi;
        unpack2(m2[j], lo, hi);
        r = fmaf(lo, qv[2 * j], r);
        r = fmaf(hi, qv[2 * j + 1], r);
    }
    r = fmaxf(r, 0.0f);
    sfin[tid] = r;
    __syncthreads();

    float oacc = bo[tid];
    #pragma unroll 8
    for (int i = 0; i < H; i++) oacc = fmaf(sfin[i], wo[(i << 6) + tid], oacc);
    out[(b << 6) + tid] = oacc;
}

// ---------------------------------------------------------------------------
// Input order (metadata): x, embed, w1, b1, w2, b2, ln_g, ln_b, wk, wv, wq, wo, bo
// ---------------------------------------------------------------------------
extern "C" void kernel_launch(void* const* d_in, const int* in_sizes, int n_in,
                              void* d_out, int out_size) {
    const int*   x     = (const int*)d_in[0];
    const float* embed = (const float*)d_in[1];
    const float* w1    = (const float*)d_in[2];
    const float* b1    = (const float*)d_in[3];
    const float* w2    = (const float*)d_in[4];
    const float* b2    = (const float*)d_in[5];
    const float* ln_g  = (const float*)d_in[6];
    const float* ln_b  = (const float*)d_in[7];
    const float* wk    = (const float*)d_in[8];
    const float* wv    = (const float*)d_in[9];
    const float* wq    = (const float*)d_in[10];
    const float* wo    = (const float*)d_in[11];
    const float* bo    = (const float*)d_in[12];
    float*       out   = (float*)d_out;

    build_tables<<<V, H>>>(embed, w1, b1, w2, b2, ln_g, ln_b, wk, wv, wq);
    scan_kernel<<<B, H>>>(x, wo, bo, out);
}